// round 15
// baseline (speedup 1.0000x reference)
#include <cuda_runtime.h>
#include <cstdint>

// ExtractPatch: B=8, H=W=1024, N=4096 matches, R=8 -> 17x17 patches.
// out[bn][k]        = normalize(img1[b, my1 + k%17 - 8, mx1 + k/17 - 8])   k in [0,289)
// out[bn][289 + k]  = normalize(img2[b, my2 + k%17 - 8, mx2 + k/17 - 8])
// normalize: (p - mean) / (std_ddof1 + 1e-4), zero-padded outside image.
//
// FINAL (best of 14 rounds, twice-confirmed): one match per warp; fused
// two-image row-major scalar gather with incremental div/mod-17 walk;
// packed-f32x2 accumulate + packed shuffle reduction; transposed smem
// staging; float2 streaming write.
// Measured: 31.2 us bench / 26.0 us ncu. Equilibrium point: compulsory
// ~5.6 KB/match of random L2 sectors at ~7 TB/s effective LTS throughput;
// occupancy / instruction-count / MLP / store-path all proven non-binding.

#define D      17
#define PATCH  289
#define HW     1024
#define NMATCH 4096
#define BATCH  8
#define WPB    4              // warps per block, one match per warp
#define THREADS (WPB * 32)

__device__ __forceinline__ uint64_t pack2(float lo, float hi) {
    uint64_t r;
    asm("mov.b64 %0, {%1, %2};" : "=l"(r) : "f"(lo), "f"(hi));
    return r;
}
__device__ __forceinline__ void unpack2(uint64_t v, float& lo, float& hi) {
    asm("mov.b64 {%0, %1}, %2;" : "=f"(lo), "=f"(hi) : "l"(v));
}
__device__ __forceinline__ uint64_t add2(uint64_t a, uint64_t b) {
    uint64_t r;
    asm("add.rn.f32x2 %0, %1, %2;" : "=l"(r) : "l"(a), "l"(b));
    return r;
}
__device__ __forceinline__ uint64_t fma2(uint64_t a, uint64_t b, uint64_t c) {
    uint64_t r;
    asm("fma.rn.f32x2 %0, %1, %2, %3;" : "=l"(r) : "l"(a), "l"(b), "l"(c));
    return r;
}
__device__ __forceinline__ uint64_t shfl_xor2(uint64_t v, int mask) {
    uint32_t lo = (uint32_t)v, hi = (uint32_t)(v >> 32);
    lo = __shfl_xor_sync(0xffffffffu, lo, mask);
    hi = __shfl_xor_sync(0xffffffffu, hi, mask);
    return (uint64_t)lo | ((uint64_t)hi << 32);
}

__global__ __launch_bounds__(THREADS, 10)
void extract_patch_kernel(const float* __restrict__ img1,
                          const float* __restrict__ img2,
                          const int*   __restrict__ matches,
                          float*       __restrict__ out)
{
    // Transposed patch buffers: T[k] = output element k (both patches concat).
    __shared__ float T[WPB][580];

    const int warpId = threadIdx.x >> 5;
    const int lane   = threadIdx.x & 31;

    const int bn = blockIdx.x * WPB + warpId;     // 0 .. 32767
    const int b  = bn >> 12;                      // NMATCH = 4096

    const float* __restrict__ ib1 = img1 + (size_t)b * (HW * HW);
    const float* __restrict__ ib2 = img2 + (size_t)b * (HW * HW);

    const int4 m = *(const int4*)(matches + bn * 4);   // mx1, my1, mx2, my2

    float* __restrict__ Tw = T[warpId];

    // initial (r, c) for this lane: idx = lane, r = idx/17, c = idx%17
    int c0 = (lane >= D) ? (lane - D) : lane;
    int r0 = (lane >= D) ? 1 : 0;

    // packed accumulators: S = (s1, s2), Q = (q1, q2)
    uint64_t S = 0, Q = 0;

    const bool interior =
        ((unsigned)(m.x - 8) <= (HW - D)) & ((unsigned)(m.y - 8) <= (HW - D)) &
        ((unsigned)(m.z - 8) <= (HW - D)) & ((unsigned)(m.w - 8) <= (HW - D));

    if (interior) {
        // ---- fast path: no per-element bounds checks ----
        const float* p1 = ib1 + (m.y - 8) * HW + (m.x - 8);
        const float* p2 = ib2 + (m.w - 8) * HW + (m.z - 8);
        int c   = c0;
        int d   = r0 * HW + c0;          // gmem offset (row-major walk)
        int sts = c0 * D + r0;           // transposed smem index = c*17 + r
        #pragma unroll
        for (int t = 0; t < 10; ++t) {
            if (t < 9 || lane == 0) {
                const float v1 = __ldg(p1 + d);
                const float v2 = __ldg(p2 + d);
                Tw[sts]         = v1;
                Tw[PATCH + sts] = v2;
                const uint64_t v = pack2(v1, v2);
                S = add2(S, v);
                Q = fma2(v, v, Q);
            }
            // advance idx by 32: c += 15, r += 1 (+carry: c -= 17, r += 1)
            c   += 15;
            d   += HW + 15;              // +1039
            sts += 15 * D + 1;           // +256
            if (c >= D) {
                c   -= D;
                d   += HW - D;           // +1007  (total carry step: +2046)
                sts -= D * D - 1;        // -288
            }
        }
    } else {
        // ---- slow path: per-element zero-padding bounds checks ----
        const int x1 = m.x - 8, y1 = m.y - 8;
        const int x2 = m.z - 8, y2 = m.w - 8;
        int c = c0, r = r0;
        int sts = c0 * D + r0;
        #pragma unroll
        for (int t = 0; t < 10; ++t) {
            if (t < 9 || lane == 0) {
                const int yy1 = y1 + r, xx1 = x1 + c;
                const int yy2 = y2 + r, xx2 = x2 + c;
                float v1 = 0.f, v2 = 0.f;
                if (((unsigned)yy1 < HW) & ((unsigned)xx1 < HW))
                    v1 = __ldg(ib1 + yy1 * HW + xx1);
                if (((unsigned)yy2 < HW) & ((unsigned)xx2 < HW))
                    v2 = __ldg(ib2 + yy2 * HW + xx2);
                Tw[sts]         = v1;
                Tw[PATCH + sts] = v2;
                const uint64_t v = pack2(v1, v2);
                S = add2(S, v);
                Q = fma2(v, v, Q);
            }
            c += 15; r += 1; sts += 15 * D + 1;
            if (c >= D) { c -= D; r += 1; sts -= D * D - 1; }
        }
    }

    // ---- packed warp reduction: shuffle both halves, add once via f32x2 ----
    #pragma unroll
    for (int o = 16; o > 0; o >>= 1) {
        S = add2(S, shfl_xor2(S, o));
        Q = add2(Q, shfl_xor2(Q, o));
    }
    float s1, s2, q1, q2;
    unpack2(S, s1, s2);
    unpack2(Q, q1, q2);

    const float mean1 = s1 * (1.0f / PATCH);
    const float mean2 = s2 * (1.0f / PATCH);
    float var1 = fmaxf((q1 - (float)PATCH * mean1 * mean1) * (1.0f / (PATCH - 1)), 0.f);
    float var2 = fmaxf((q2 - (float)PATCH * mean2 * mean2) * (1.0f / (PATCH - 1)), 0.f);
    const float inv1 = 1.0f / (sqrtf(var1) + 1e-4f);
    const float inv2 = 1.0f / (sqrtf(var2) + 1e-4f);
    const float bb1  = -mean1 * inv1;   // (v - m)*i = v*i + (-m*i)
    const float bb2  = -mean2 * inv2;

    // packed normalize coefficients per patch
    const uint64_t A1 = pack2(inv1, inv1), B1 = pack2(bb1, bb1);
    const uint64_t A2 = pack2(inv2, inv2), B2 = pack2(bb2, bb2);

    __syncwarp();

    // ---- vectorized normalized write: 289 float2 over 578 contiguous floats ----
    float2* __restrict__ ob = (float2*)(out + (size_t)bn * (2 * PATCH));
    const uint64_t* __restrict__ Ts = (const uint64_t*)Tw;   // 8B aligned

    #pragma unroll
    for (int t = 0; t < 10; ++t) {
        const int k = t * 32 + lane;      // float2 index, valid k < 289
        if (t < 9 || lane == 0) {
            const uint64_t v = Ts[k];
            uint64_t A, B;
            if (t < 4)      { A = A1; B = B1; }
            else if (t > 4) { A = A2; B = B2; }
            else {
                // boundary tile: elem 2k is patch1 iff k<=144; elem 2k+1 patch1 iff k<=143
                const float aLo = (k <= 144) ? inv1 : inv2, bLo = (k <= 144) ? bb1 : bb2;
                const float aHi = (k <= 143) ? inv1 : inv2, bHi = (k <= 143) ? bb1 : bb2;
                A = pack2(aLo, aHi); B = pack2(bLo, bHi);
            }
            const uint64_t w = fma2(v, A, B);
            float wlo, whi;
            unpack2(w, wlo, whi);
            __stcs(&ob[k], make_float2(wlo, whi));
        }
    }
}

extern "C" void kernel_launch(void* const* d_in, const int* in_sizes, int n_in,
                              void* d_out, int out_size)
{
    const float* img1    = (const float*)d_in[0];
    const float* img2    = (const float*)d_in[1];
    const int*   matches = (const int*)d_in[2];
    float*       out     = (float*)d_out;

    const int total_matches = BATCH * NMATCH;           // 32768
    const int blocks = total_matches / WPB;             // 8192

    extract_patch_kernel<<<blocks, THREADS>>>(img1, img2, matches, out);
}

// round 16
// speedup vs baseline: 1.0041x; 1.0041x over previous
#include <cuda_runtime.h>
#include <cstdint>

// ExtractPatch: B=8, H=W=1024, N=4096 matches, R=8 -> 17x17 patches.
// out[bn][k]        = normalize(img1[b, my1 + k%17 - 8, mx1 + k/17 - 8])   k in [0,289)
// out[bn][289 + k]  = normalize(img2[b, my2 + k%17 - 8, mx2 + k/17 - 8])
// normalize: (p - mean) / (std_ddof1 + 1e-4), zero-padded outside image.
//
// FINAL (best of 15 rounds, thrice-confirmed at 31.2 us bench / ~26 us ncu):
// one match per warp; fused two-image row-major scalar gather with
// incremental div/mod-17 walk; packed-f32x2 accumulate + packed shuffle
// reduction; transposed smem staging; float2 streaming write.
// Floor analysis: compulsory ~5.6 KB/match of random L2 sectors (two
// 17-row x 3-sector gathers + 2.3 KB write) at ~7 TB/s effective LTS;
// occupancy / instruction count / MLP / store path all proven non-binding.

#define D      17
#define PATCH  289
#define HW     1024
#define NMATCH 4096
#define BATCH  8
#define WPB    4              // warps per block, one match per warp
#define THREADS (WPB * 32)

__device__ __forceinline__ uint64_t pack2(float lo, float hi) {
    uint64_t r;
    asm("mov.b64 %0, {%1, %2};" : "=l"(r) : "f"(lo), "f"(hi));
    return r;
}
__device__ __forceinline__ void unpack2(uint64_t v, float& lo, float& hi) {
    asm("mov.b64 {%0, %1}, %2;" : "=f"(lo), "=f"(hi) : "l"(v));
}
__device__ __forceinline__ uint64_t add2(uint64_t a, uint64_t b) {
    uint64_t r;
    asm("add.rn.f32x2 %0, %1, %2;" : "=l"(r) : "l"(a), "l"(b));
    return r;
}
__device__ __forceinline__ uint64_t fma2(uint64_t a, uint64_t b, uint64_t c) {
    uint64_t r;
    asm("fma.rn.f32x2 %0, %1, %2, %3;" : "=l"(r) : "l"(a), "l"(b), "l"(c));
    return r;
}
__device__ __forceinline__ uint64_t shfl_xor2(uint64_t v, int mask) {
    uint32_t lo = (uint32_t)v, hi = (uint32_t)(v >> 32);
    lo = __shfl_xor_sync(0xffffffffu, lo, mask);
    hi = __shfl_xor_sync(0xffffffffu, hi, mask);
    return (uint64_t)lo | ((uint64_t)hi << 32);
}

__global__ __launch_bounds__(THREADS, 10)
void extract_patch_kernel(const float* __restrict__ img1,
                          const float* __restrict__ img2,
                          const int*   __restrict__ matches,
                          float*       __restrict__ out)
{
    // Transposed patch buffers: T[k] = output element k (both patches concat).
    __shared__ float T[WPB][580];

    const int warpId = threadIdx.x >> 5;
    const int lane   = threadIdx.x & 31;

    const int bn = blockIdx.x * WPB + warpId;     // 0 .. 32767
    const int b  = bn >> 12;                      // NMATCH = 4096

    const float* __restrict__ ib1 = img1 + (size_t)b * (HW * HW);
    const float* __restrict__ ib2 = img2 + (size_t)b * (HW * HW);

    const int4 m = *(const int4*)(matches + bn * 4);   // mx1, my1, mx2, my2

    float* __restrict__ Tw = T[warpId];

    // initial (r, c) for this lane: idx = lane, r = idx/17, c = idx%17
    int c0 = (lane >= D) ? (lane - D) : lane;
    int r0 = (lane >= D) ? 1 : 0;

    // packed accumulators: S = (s1, s2), Q = (q1, q2)
    uint64_t S = 0, Q = 0;

    const bool interior =
        ((unsigned)(m.x - 8) <= (HW - D)) & ((unsigned)(m.y - 8) <= (HW - D)) &
        ((unsigned)(m.z - 8) <= (HW - D)) & ((unsigned)(m.w - 8) <= (HW - D));

    if (interior) {
        // ---- fast path: no per-element bounds checks ----
        const float* p1 = ib1 + (m.y - 8) * HW + (m.x - 8);
        const float* p2 = ib2 + (m.w - 8) * HW + (m.z - 8);
        int c   = c0;
        int d   = r0 * HW + c0;          // gmem offset (row-major walk)
        int sts = c0 * D + r0;           // transposed smem index = c*17 + r
        #pragma unroll
        for (int t = 0; t < 10; ++t) {
            if (t < 9 || lane == 0) {
                const float v1 = __ldg(p1 + d);
                const float v2 = __ldg(p2 + d);
                Tw[sts]         = v1;
                Tw[PATCH + sts] = v2;
                const uint64_t v = pack2(v1, v2);
                S = add2(S, v);
                Q = fma2(v, v, Q);
            }
            // advance idx by 32: c += 15, r += 1 (+carry: c -= 17, r += 1)
            c   += 15;
            d   += HW + 15;              // +1039
            sts += 15 * D + 1;           // +256
            if (c >= D) {
                c   -= D;
                d   += HW - D;           // +1007  (total carry step: +2046)
                sts -= D * D - 1;        // -288
            }
        }
    } else {
        // ---- slow path: per-element zero-padding bounds checks ----
        const int x1 = m.x - 8, y1 = m.y - 8;
        const int x2 = m.z - 8, y2 = m.w - 8;
        int c = c0, r = r0;
        int sts = c0 * D + r0;
        #pragma unroll
        for (int t = 0; t < 10; ++t) {
            if (t < 9 || lane == 0) {
                const int yy1 = y1 + r, xx1 = x1 + c;
                const int yy2 = y2 + r, xx2 = x2 + c;
                float v1 = 0.f, v2 = 0.f;
                if (((unsigned)yy1 < HW) & ((unsigned)xx1 < HW))
                    v1 = __ldg(ib1 + yy1 * HW + xx1);
                if (((unsigned)yy2 < HW) & ((unsigned)xx2 < HW))
                    v2 = __ldg(ib2 + yy2 * HW + xx2);
                Tw[sts]         = v1;
                Tw[PATCH + sts] = v2;
                const uint64_t v = pack2(v1, v2);
                S = add2(S, v);
                Q = fma2(v, v, Q);
            }
            c += 15; r += 1; sts += 15 * D + 1;
            if (c >= D) { c -= D; r += 1; sts -= D * D - 1; }
        }
    }

    // ---- packed warp reduction: shuffle both halves, add once via f32x2 ----
    #pragma unroll
    for (int o = 16; o > 0; o >>= 1) {
        S = add2(S, shfl_xor2(S, o));
        Q = add2(Q, shfl_xor2(Q, o));
    }
    float s1, s2, q1, q2;
    unpack2(S, s1, s2);
    unpack2(Q, q1, q2);

    const float mean1 = s1 * (1.0f / PATCH);
    const float mean2 = s2 * (1.0f / PATCH);
    float var1 = fmaxf((q1 - (float)PATCH * mean1 * mean1) * (1.0f / (PATCH - 1)), 0.f);
    float var2 = fmaxf((q2 - (float)PATCH * mean2 * mean2) * (1.0f / (PATCH - 1)), 0.f);
    const float inv1 = 1.0f / (sqrtf(var1) + 1e-4f);
    const float inv2 = 1.0f / (sqrtf(var2) + 1e-4f);
    const float bb1  = -mean1 * inv1;   // (v - m)*i = v*i + (-m*i)
    const float bb2  = -mean2 * inv2;

    // packed normalize coefficients per patch
    const uint64_t A1 = pack2(inv1, inv1), B1 = pack2(bb1, bb1);
    const uint64_t A2 = pack2(inv2, inv2), B2 = pack2(bb2, bb2);

    __syncwarp();

    // ---- vectorized normalized write: 289 float2 over 578 contiguous floats ----
    float2* __restrict__ ob = (float2*)(out + (size_t)bn * (2 * PATCH));
    const uint64_t* __restrict__ Ts = (const uint64_t*)Tw;   // 8B aligned

    #pragma unroll
    for (int t = 0; t < 10; ++t) {
        const int k = t * 32 + lane;      // float2 index, valid k < 289
        if (t < 9 || lane == 0) {
            const uint64_t v = Ts[k];
            uint64_t A, B;
            if (t < 4)      { A = A1; B = B1; }
            else if (t > 4) { A = A2; B = B2; }
            else {
                // boundary tile: elem 2k is patch1 iff k<=144; elem 2k+1 patch1 iff k<=143
                const float aLo = (k <= 144) ? inv1 : inv2, bLo = (k <= 144) ? bb1 : bb2;
                const float aHi = (k <= 143) ? inv1 : inv2, bHi = (k <= 143) ? bb1 : bb2;
                A = pack2(aLo, aHi); B = pack2(bLo, bHi);
            }
            const uint64_t w = fma2(v, A, B);
            float wlo, whi;
            unpack2(w, wlo, whi);
            __stcs(&ob[k], make_float2(wlo, whi));
        }
    }
}

extern "C" void kernel_launch(void* const* d_in, const int* in_sizes, int n_in,
                              void* d_out, int out_size)
{
    const float* img1    = (const float*)d_in[0];
    const float* img2    = (const float*)d_in[1];
    const int*   matches = (const int*)d_in[2];
    float*       out     = (float*)d_out;

    const int total_matches = BATCH * NMATCH;           // 32768
    const int blocks = total_matches / WPB;             // 8192

    extract_patch_kernel<<<blocks, THREADS>>>(img1, img2, matches, out);
}

// round 17
// speedup vs baseline: 1.0051x; 1.0010x over previous
#include <cuda_runtime.h>
#include <cstdint>

// ExtractPatch: B=8, H=W=1024, N=4096 matches, R=8 -> 17x17 patches.
// out[bn][k]        = normalize(img1[b, my1 + k%17 - 8, mx1 + k/17 - 8])   k in [0,289)
// out[bn][289 + k]  = normalize(img2[b, my2 + k%17 - 8, mx2 + k/17 - 8])
// normalize: (p - mean) / (std_ddof1 + 1e-4), zero-padded outside image.
//
// FINAL (best of 16 rounds, 4x-confirmed at ~31.1 us bench / ~26.1 us ncu):
// one match per warp; fused two-image row-major scalar gather with
// incremental div/mod-17 walk; packed-f32x2 accumulate + packed shuffle
// reduction; transposed smem staging; float2 streaming write.
// Floor: compulsory ~5.6 KB/match random L2 sector traffic (two 17-row x
// 3-sector gathers + 2.3 KB write; images L2-resident, DRAM carries only
// the output stream) with issue/L1 balanced below saturation. Occupancy,
// instruction count, per-warp MLP, and store path each independently
// falsified as binding constraints (R2/R5/R6/R8-R13).

#define D      17
#define PATCH  289
#define HW     1024
#define NMATCH 4096
#define BATCH  8
#define WPB    4              // warps per block, one match per warp
#define THREADS (WPB * 32)

__device__ __forceinline__ uint64_t pack2(float lo, float hi) {
    uint64_t r;
    asm("mov.b64 %0, {%1, %2};" : "=l"(r) : "f"(lo), "f"(hi));
    return r;
}
__device__ __forceinline__ void unpack2(uint64_t v, float& lo, float& hi) {
    asm("mov.b64 {%0, %1}, %2;" : "=f"(lo), "=f"(hi) : "l"(v));
}
__device__ __forceinline__ uint64_t add2(uint64_t a, uint64_t b) {
    uint64_t r;
    asm("add.rn.f32x2 %0, %1, %2;" : "=l"(r) : "l"(a), "l"(b));
    return r;
}
__device__ __forceinline__ uint64_t fma2(uint64_t a, uint64_t b, uint64_t c) {
    uint64_t r;
    asm("fma.rn.f32x2 %0, %1, %2, %3;" : "=l"(r) : "l"(a), "l"(b), "l"(c));
    return r;
}
__device__ __forceinline__ uint64_t shfl_xor2(uint64_t v, int mask) {
    uint32_t lo = (uint32_t)v, hi = (uint32_t)(v >> 32);
    lo = __shfl_xor_sync(0xffffffffu, lo, mask);
    hi = __shfl_xor_sync(0xffffffffu, hi, mask);
    return (uint64_t)lo | ((uint64_t)hi << 32);
}

__global__ __launch_bounds__(THREADS, 10)
void extract_patch_kernel(const float* __restrict__ img1,
                          const float* __restrict__ img2,
                          const int*   __restrict__ matches,
                          float*       __restrict__ out)
{
    // Transposed patch buffers: T[k] = output element k (both patches concat).
    __shared__ float T[WPB][580];

    const int warpId = threadIdx.x >> 5;
    const int lane   = threadIdx.x & 31;

    const int bn = blockIdx.x * WPB + warpId;     // 0 .. 32767
    const int b  = bn >> 12;                      // NMATCH = 4096

    const float* __restrict__ ib1 = img1 + (size_t)b * (HW * HW);
    const float* __restrict__ ib2 = img2 + (size_t)b * (HW * HW);

    const int4 m = *(const int4*)(matches + bn * 4);   // mx1, my1, mx2, my2

    float* __restrict__ Tw = T[warpId];

    // initial (r, c) for this lane: idx = lane, r = idx/17, c = idx%17
    int c0 = (lane >= D) ? (lane - D) : lane;
    int r0 = (lane >= D) ? 1 : 0;

    // packed accumulators: S = (s1, s2), Q = (q1, q2)
    uint64_t S = 0, Q = 0;

    const bool interior =
        ((unsigned)(m.x - 8) <= (HW - D)) & ((unsigned)(m.y - 8) <= (HW - D)) &
        ((unsigned)(m.z - 8) <= (HW - D)) & ((unsigned)(m.w - 8) <= (HW - D));

    if (interior) {
        // ---- fast path: no per-element bounds checks ----
        const float* p1 = ib1 + (m.y - 8) * HW + (m.x - 8);
        const float* p2 = ib2 + (m.w - 8) * HW + (m.z - 8);
        int c   = c0;
        int d   = r0 * HW + c0;          // gmem offset (row-major walk)
        int sts = c0 * D + r0;           // transposed smem index = c*17 + r
        #pragma unroll
        for (int t = 0; t < 10; ++t) {
            if (t < 9 || lane == 0) {
                const float v1 = __ldg(p1 + d);
                const float v2 = __ldg(p2 + d);
                Tw[sts]         = v1;
                Tw[PATCH + sts] = v2;
                const uint64_t v = pack2(v1, v2);
                S = add2(S, v);
                Q = fma2(v, v, Q);
            }
            // advance idx by 32: c += 15, r += 1 (+carry: c -= 17, r += 1)
            c   += 15;
            d   += HW + 15;              // +1039
            sts += 15 * D + 1;           // +256
            if (c >= D) {
                c   -= D;
                d   += HW - D;           // +1007  (total carry step: +2046)
                sts -= D * D - 1;        // -288
            }
        }
    } else {
        // ---- slow path: per-element zero-padding bounds checks ----
        const int x1 = m.x - 8, y1 = m.y - 8;
        const int x2 = m.z - 8, y2 = m.w - 8;
        int c = c0, r = r0;
        int sts = c0 * D + r0;
        #pragma unroll
        for (int t = 0; t < 10; ++t) {
            if (t < 9 || lane == 0) {
                const int yy1 = y1 + r, xx1 = x1 + c;
                const int yy2 = y2 + r, xx2 = x2 + c;
                float v1 = 0.f, v2 = 0.f;
                if (((unsigned)yy1 < HW) & ((unsigned)xx1 < HW))
                    v1 = __ldg(ib1 + yy1 * HW + xx1);
                if (((unsigned)yy2 < HW) & ((unsigned)xx2 < HW))
                    v2 = __ldg(ib2 + yy2 * HW + xx2);
                Tw[sts]         = v1;
                Tw[PATCH + sts] = v2;
                const uint64_t v = pack2(v1, v2);
                S = add2(S, v);
                Q = fma2(v, v, Q);
            }
            c += 15; r += 1; sts += 15 * D + 1;
            if (c >= D) { c -= D; r += 1; sts -= D * D - 1; }
        }
    }

    // ---- packed warp reduction: shuffle both halves, add once via f32x2 ----
    #pragma unroll
    for (int o = 16; o > 0; o >>= 1) {
        S = add2(S, shfl_xor2(S, o));
        Q = add2(Q, shfl_xor2(Q, o));
    }
    float s1, s2, q1, q2;
    unpack2(S, s1, s2);
    unpack2(Q, q1, q2);

    const float mean1 = s1 * (1.0f / PATCH);
    const float mean2 = s2 * (1.0f / PATCH);
    float var1 = fmaxf((q1 - (float)PATCH * mean1 * mean1) * (1.0f / (PATCH - 1)), 0.f);
    float var2 = fmaxf((q2 - (float)PATCH * mean2 * mean2) * (1.0f / (PATCH - 1)), 0.f);
    const float inv1 = 1.0f / (sqrtf(var1) + 1e-4f);
    const float inv2 = 1.0f / (sqrtf(var2) + 1e-4f);
    const float bb1  = -mean1 * inv1;   // (v - m)*i = v*i + (-m*i)
    const float bb2  = -mean2 * inv2;

    // packed normalize coefficients per patch
    const uint64_t A1 = pack2(inv1, inv1), B1 = pack2(bb1, bb1);
    const uint64_t A2 = pack2(inv2, inv2), B2 = pack2(bb2, bb2);

    __syncwarp();

    // ---- vectorized normalized write: 289 float2 over 578 contiguous floats ----
    float2* __restrict__ ob = (float2*)(out + (size_t)bn * (2 * PATCH));
    const uint64_t* __restrict__ Ts = (const uint64_t*)Tw;   // 8B aligned

    #pragma unroll
    for (int t = 0; t < 10; ++t) {
        const int k = t * 32 + lane;      // float2 index, valid k < 289
        if (t < 9 || lane == 0) {
            const uint64_t v = Ts[k];
            uint64_t A, B;
            if (t < 4)      { A = A1; B = B1; }
            else if (t > 4) { A = A2; B = B2; }
            else {
                // boundary tile: elem 2k is patch1 iff k<=144; elem 2k+1 patch1 iff k<=143
                const float aLo = (k <= 144) ? inv1 : inv2, bLo = (k <= 144) ? bb1 : bb2;
                const float aHi = (k <= 143) ? inv1 : inv2, bHi = (k <= 143) ? bb1 : bb2;
                A = pack2(aLo, aHi); B = pack2(bLo, bHi);
            }
            const uint64_t w = fma2(v, A, B);
            float wlo, whi;
            unpack2(w, wlo, whi);
            __stcs(&ob[k], make_float2(wlo, whi));
        }
    }
}

extern "C" void kernel_launch(void* const* d_in, const int* in_sizes, int n_in,
                              void* d_out, int out_size)
{
    const float* img1    = (const float*)d_in[0];
    const float* img2    = (const float*)d_in[1];
    const int*   matches = (const int*)d_in[2];
    float*       out     = (float*)d_out;

    const int total_matches = BATCH * NMATCH;           // 32768
    const int blocks = total_matches / WPB;             // 8192

    extract_patch_kernel<<<blocks, THREADS>>>(img1, img2, matches, out);
}